// round 7
// baseline (speedup 1.0000x reference)
#include <cuda_runtime.h>
#include <cuda_bf16.h>

#define DIM        128
#define MAX_ENT    50048
#define MAX_REL    24
#define MAX_NEEDED 4096
#define NBLK_A     148
#define NTHR_A     1024
#define GROUPS     2

// ---------------- device scratch (static zero-init; epoch-tagged) ---------
// g_slot[node] = (epoch+1)<<13 | code. code: 1 = claiming, s+2 = slot s.
// A node is "current" iff its tag equals this call's epoch+1, so the slot
// table NEVER needs cleaning. Barriers use monotonic counters keyed to epoch.
__device__ unsigned long long g_epoch;                // incremented once/call
__device__ unsigned long long g_barA;                 // monotonic counters
__device__ unsigned long long g_barB;
__device__ unsigned long long g_slot[MAX_ENT];
__device__ unsigned int       g_bits[MAX_ENT / 32];   // membership bitmap
__device__ int                g_needed_nodes[MAX_NEEDED];
__device__ int                g_n_needed;
__device__ float              g_msg[(size_t)MAX_NEEDED * MAX_REL * DIM];
__device__ float              g_cnt[MAX_NEEDED * MAX_REL];
__device__ float              g_agg[2][MAX_NEEDED * DIM];   // parity buffers

__device__ __forceinline__ int ld_idx(const void* p, size_t i, int is64) {
    if (is64) return (int)((const long long*)p)[i];
    return ((const int*)p)[i];
}

// fast tanh: 1 - 2/(e^{2x}+1); rel err ~1e-7
__device__ __forceinline__ float ftanh(float x) {
    float e = __expf(2.0f * x);
    return 1.0f - 2.0f / (e + 1.0f);
}

// Monotonic grid barrier. All blocks of the kernel are co-resident
// (grid <= 148 blocks, each fits one SM), so spinning cannot deadlock.
__device__ __forceinline__ void grid_barrier(unsigned long long* ctr,
                                             unsigned long long target) {
    __threadfence();
    __syncthreads();
    if (threadIdx.x == 0) {
        atomicAdd(ctr, 1ULL);
        while (*(volatile unsigned long long*)ctr < target) { }
        __threadfence();
    }
    __syncthreads();
}

// =================== K_A: detect + mark/compact | barrier | edge scan ======
__global__ void __launch_bounds__(NTHR_A)
k_a(const void* __restrict__ edge_index,
    const void* __restrict__ edge_type,
    const float* __restrict__ x,
    const void* __restrict__ sample,
    int n_edge, int n_rel, int batch) {
    __shared__ int s_any;
    const int tid  = threadIdx.x;
    const int gtid = blockIdx.x * NTHR_A + tid;
    const int gsz  = gridDim.x * NTHR_A;
    const unsigned long long e = *(volatile unsigned long long*)&g_epoch;

    // dtype detect: non-negative int64 => high 32-bit words all zero
    if (tid == 0) s_any = 0;
    __syncthreads();
    if (tid < 256 && ((const unsigned int*)edge_index)[tid * 2 + 1] != 0u)
        atomicOr(&s_any, 1);
    __syncthreads();
    const int is64 = s_any ? 0 : 1;

    // ---- phase 1: mark + compact (sample columns 0 and 2) ----------------
    const unsigned long long tagbase = (e + 1) << 13;
    for (int i = gtid; i < batch * 2; i += gsz) {
        int b = i >> 1;
        int c = (i & 1) * 2;
        int node = ld_idx(sample, (size_t)b * 3 + c, is64);
        unsigned long long old = atomicMax(&g_slot[node], tagbase | 1ULL);
        if (old < tagbase) {                       // unique winner this epoch
            int s = atomicAdd(&g_n_needed, 1);
            g_needed_nodes[s] = node;
            atomicOr(&g_bits[node >> 5], 1u << (node & 31));
            atomicMax(&g_slot[node], tagbase | (unsigned long long)(s + 2));
        }
    }
    grid_barrier(&g_barA, (e + 1) * (unsigned long long)gridDim.x);

    // ---- phase 2: edge scan (4 edges/unit, bitmap reject) ----------------
    int nq = (n_edge + 3) >> 2;
    for (int q = gtid; q < nq; q += gsz) {
        int e0 = q * 4;
        int nv = (e0 + 4 <= n_edge) ? 4 : (n_edge - e0);
        int dst[4];
        if (nv == 4) {
            if (!is64) {
                int4 v = *(const int4*)((const int*)edge_index + (size_t)n_edge + e0);
                dst[0] = v.x; dst[1] = v.y; dst[2] = v.z; dst[3] = v.w;
            } else {
                longlong2 a = *(const longlong2*)((const long long*)edge_index + (size_t)n_edge + e0);
                longlong2 b = *(const longlong2*)((const long long*)edge_index + (size_t)n_edge + e0 + 2);
                dst[0] = (int)a.x; dst[1] = (int)a.y; dst[2] = (int)b.x; dst[3] = (int)b.y;
            }
        } else {
            for (int k = 0; k < nv; k++)
                dst[k] = ld_idx(edge_index, (size_t)n_edge + e0 + k, is64);
        }
#pragma unroll
        for (int k = 0; k < 4; k++) {
            if (k >= nv) break;
            if (!(g_bits[dst[k] >> 5] & (1u << (dst[k] & 31)))) continue;
            int s = (int)(g_slot[dst[k]] & 8191ULL) - 2;
            int ee  = e0 + k;
            int r   = ld_idx(edge_type, ee, is64);
            int src = ld_idx(edge_index, ee, is64);
            atomicAdd(&g_cnt[s * n_rel + r], 1.0f);
            const float4* xs = (const float4*)(x + (size_t)src * DIM);
            float* m = &g_msg[((size_t)s * n_rel + r) * DIM];
#pragma unroll
            for (int j = 0; j < DIM / 4; j++) {
                float4 v = xs[j];
                atomicAdd(&m[4 * j + 0], v.x);
                atomicAdd(&m[4 * j + 1], v.y);
                atomicAdd(&m[4 * j + 2], v.z);
                atomicAdd(&m[4 * j + 3], v.w);
            }
        }
    }
}

// =================== K_B: gemm | barrier | out + cleanup ===================
// grid = (n_rel+1)*2*GROUPS = 100 blocks of 128 threads (co-resident).
__global__ void __launch_bounds__(128)
k_b(const float* __restrict__ W_rel,
    const float* __restrict__ W_root,
    const float* __restrict__ x,
    const void* __restrict__ sample,
    const float* __restrict__ init_rel,
    float* __restrict__ out,
    int n_rel, int batch, int is64_probe_unused) {
    __shared__ float Ws[64 * DIM];   // one 64-col half of a W matrix
    __shared__ float ms[DIM];

    const int tid = threadIdx.x;
    const unsigned long long e = *(volatile unsigned long long*)&g_epoch;
    const int b = (int)(e & 1ULL);
    float* agg  = g_agg[b];
    float* agg2 = g_agg[1 - b];
    const int nn = g_n_needed;

    // ---- phase 1: gemm ----------------------------------------------------
    {
        int idx  = blockIdx.x;
        int r    = idx % (n_rel + 1);
        int half = (idx / (n_rel + 1)) & 1;
        int sg   = idx / ((n_rel + 1) * 2);
        const float* W = (r < n_rel) ? (W_rel + (size_t)r * DIM * DIM) : W_root;
        int fbase = half * 64;

        for (int i = tid; i < 64 * DIM / 4; i += 128) {
            int d = i >> 4, c4 = i & 15;
            ((float4*)Ws)[d * 16 + c4] = *(const float4*)&W[d * DIM + fbase + c4 * 4];
        }
        __syncthreads();

        int c  = tid & 63;
        int dh = (tid >> 6) * 64;

        for (int s = sg; s < nn; s += GROUPS) {
            bool skip = false;
            float scale = 1.0f;
            if (r < n_rel) {
                float cnt = g_cnt[s * n_rel + r];      // uniform across block
                if (cnt == 0.0f) skip = true;
                else scale = 1.0f / cnt;
            }
            if (!skip) {
                if (r < n_rel)
                    ms[tid] = g_msg[((size_t)s * n_rel + r) * DIM + tid] * scale;
                else
                    ms[tid] = x[(size_t)g_needed_nodes[s] * DIM + tid];
            }
            __syncthreads();
            if (!skip) {
                float acc = 0.0f;
#pragma unroll
                for (int k = 0; k < 16; k++) {
                    int d = dh + k * 4;
                    float4 mv = *(const float4*)&ms[d];
                    acc += mv.x * Ws[(d + 0) * 64 + c];
                    acc += mv.y * Ws[(d + 1) * 64 + c];
                    acc += mv.z * Ws[(d + 2) * 64 + c];
                    acc += mv.w * Ws[(d + 3) * 64 + c];
                }
                atomicAdd(&agg[s * DIM + fbase + c], acc);
            }
            __syncthreads();
        }
    }
    grid_barrier(&g_barB, (e + 1) * (unsigned long long)gridDim.x);

    // ---- phase 2: warp-per-row gather epilogue ----------------------------
    const int gtid  = blockIdx.x * 128 + tid;
    const int gsz   = gridDim.x * 128;
    const int lane  = tid & 31;
    const int warps = gsz >> 5;

    // dtype of sample: re-detect cheaply from slot semantics is impossible;
    // probe sample's high words directly (batch*3 >= 256 elements).
    int is64;
    {
        unsigned int hw = ((const unsigned int*)sample)[(lane * 7 + 1) * 2 + 1];
        unsigned int any = __ballot_sync(0xffffffffu, hw != 0u);
        is64 = any ? 0 : 1;
    }

    for (int w = gtid >> 5; w < batch; w += warps) {
        int sh = 0, st = 0, rel = 0;
        if (lane == 0) {
            int h = ld_idx(sample, (size_t)w * 3 + 0, is64);
            rel   = ld_idx(sample, (size_t)w * 3 + 1, is64);
            int t = ld_idx(sample, (size_t)w * 3 + 2, is64);
            sh = (int)(g_slot[h] & 8191ULL) - 2;
            st = (int)(g_slot[t] & 8191ULL) - 2;
        }
        sh  = __shfl_sync(0xffffffffu, sh, 0);
        st  = __shfl_sync(0xffffffffu, st, 0);
        rel = __shfl_sync(0xffffffffu, rel, 0);

        float4 ah = ((const float4*)agg)[sh * (DIM / 4) + lane];
        float4 at = ((const float4*)agg)[st * (DIM / 4) + lane];
        float4 rv = ((const float4*)init_rel)[rel * (DIM / 4) + lane];
        float4 o;
        o.x = ftanh(ah.x) * (rv.x * ftanh(at.x));
        o.y = ftanh(ah.y) * (rv.y * ftanh(at.y));
        o.z = ftanh(ah.z) * (rv.z * ftanh(at.z));
        o.w = ftanh(ah.w) * (rv.w * ftanh(at.w));
        ((float4*)out)[(size_t)w * (DIM / 4) + lane] = o;
    }

    // ---- phase 3: cleanup for next call (none of this is read above) ------
    {
        float4 z = make_float4(0.f, 0.f, 0.f, 0.f);
        int n_msg4 = nn * n_rel * (DIM / 4);
        for (int i = gtid; i < n_msg4; i += gsz) ((float4*)g_msg)[i] = z;
        int n_cnt = nn * n_rel;
        for (int i = gtid; i < n_cnt; i += gsz) g_cnt[i] = 0.0f;
        int n_agg4 = nn * (DIM / 4);
        for (int i = gtid; i < n_agg4; i += gsz) ((float4*)agg2)[i] = z;
        for (int i = gtid; i < nn; i += gsz) {
            int node = g_needed_nodes[i];
            g_bits[node >> 5] = 0u;
        }
        if (gtid == 0) {
            g_n_needed = 0;
            __threadfence();
            atomicAdd(&g_epoch, 1ULL);     // publish next epoch last
        }
    }
}

// ---------------- launch ----------------
extern "C" void kernel_launch(void* const* d_in, const int* in_sizes, int n_in,
                              void* d_out, int out_size) {
    const float* init_embed = (const float*)d_in[0];
    const float* init_rel   = (const float*)d_in[1];
    const float* W_rel      = (const float*)d_in[2];
    const float* W_root     = (const float*)d_in[3];
    const void*  edge_index = d_in[4];
    const void*  edge_type  = d_in[5];
    const void*  sample     = d_in[6];
    float* out = (float*)d_out;

    int n_rel  = in_sizes[1] / DIM;
    int n_edge = in_sizes[5];
    int batch  = in_sizes[6] / 3;

    k_a<<<NBLK_A, NTHR_A>>>(edge_index, edge_type, init_embed, sample,
                            n_edge, n_rel, batch);
    k_b<<<(n_rel + 1) * 2 * GROUPS, 128>>>(W_rel, W_root, init_embed, sample,
                                           init_rel, out, n_rel, batch, 0);
}

// round 8
// speedup vs baseline: 1.6128x; 1.6128x over previous
#include <cuda_runtime.h>
#include <cuda_bf16.h>

#define DIM        128
#define MAX_ENT    50048
#define MAX_REL    24
#define MAX_NEEDED 4096
#define GROUPS     8
#define MS_BLK     592          // 148 SMs x 4 blocks (co-resident by design)
#define OC_BLK     256

// ---------------- device scratch (static zero-init == "clean" state) ------
// g_slot[node]: 0 = free, 1 = being claimed, s+2 = assigned slot s
__device__ int          g_is64;
__device__ int          g_slot[MAX_ENT];
__device__ unsigned int g_bits[MAX_ENT / 32];        // membership bitmap
__device__ int          g_needed_nodes[MAX_NEEDED];
__device__ int          g_n_needed;
__device__ float        g_msg[(size_t)MAX_NEEDED * MAX_REL * DIM];
__device__ float        g_cnt[MAX_NEEDED * MAX_REL];
__device__ float        g_agg[MAX_NEEDED * DIM];
// sense-reversal barriers (count self-resets to 0; sense flips per use)
__device__ unsigned int g_cntA, g_senseA;
__device__ unsigned int g_cntB, g_senseB;

__device__ __forceinline__ int ld_idx(const void* p, size_t i, int is64) {
    if (is64) return (int)((const long long*)p)[i];
    return ((const int*)p)[i];
}

// fast tanh: 1 - 2/(e^{2x}+1); rel err ~1e-7
__device__ __forceinline__ float ftanh(float x) {
    float e = __expf(2.0f * x);
    return 1.0f - 2.0f / (e + 1.0f);
}

// Sense-reversal grid barrier. Self-resetting (replay-safe): last arriver
// zeroes the counter and flips the sense. All blocks of the calling kernel
// are co-resident (grid sized for guaranteed residency), so spinning is safe.
__device__ __forceinline__ void barrier_sr(unsigned int* cnt,
                                           unsigned int* sense,
                                           unsigned int nblk) {
    __threadfence();                       // publish phase-1 writes
    __syncthreads();
    if (threadIdx.x == 0) {
        unsigned int my_sense = *(volatile unsigned int*)sense;  // pre-arrive
        unsigned int v = atomicAdd(cnt, 1u);
        if (v == nblk - 1u) {
            atomicExch(cnt, 0u);           // reset for next call
            __threadfence();
            atomicExch(sense, my_sense ^ 1u);   // release
        } else {
            while (*(volatile unsigned int*)sense == my_sense) { }
        }
        __threadfence();
    }
    __syncthreads();
}

// ============ 1) k_ms: detect + mark/compact | barrier | edge scan =========
__global__ void __launch_bounds__(256, 4)
k_ms(const void* __restrict__ edge_index,
     const void* __restrict__ edge_type,
     const float* __restrict__ x,
     const void* __restrict__ sample,
     int n_edge, int n_rel, int batch) {
    __shared__ int s_any;
    const int tid  = threadIdx.x;
    const int gtid = blockIdx.x * 256 + tid;
    const int gsz  = gridDim.x * 256;

    // dtype detect: non-negative int64 => high 32-bit words all zero
    if (tid == 0) s_any = 0;
    __syncthreads();
    if (((const unsigned int*)edge_index)[tid * 2 + 1] != 0u) atomicOr(&s_any, 1);
    __syncthreads();
    const int is64 = s_any ? 0 : 1;
    if (gtid == 0) g_is64 = is64;

    // ---- phase 1: mark + compact (sample columns 0 and 2) ----------------
    for (int i = gtid; i < batch * 2; i += gsz) {
        int b = i >> 1;
        int c = (i & 1) * 2;
        int node = ld_idx(sample, (size_t)b * 3 + c, is64);
        if (atomicCAS(&g_slot[node], 0, 1) == 0) {   // unique claimer
            int s = atomicAdd(&g_n_needed, 1);
            g_needed_nodes[s] = node;
            atomicOr(&g_bits[node >> 5], 1u << (node & 31));
            g_slot[node] = s + 2;
        }
    }
    barrier_sr(&g_cntA, &g_senseA, gridDim.x);

    // ---- phase 2: edge scan (4 edges/unit, bitmap reject) ----------------
    int nq = (n_edge + 3) >> 2;
    for (int q = gtid; q < nq; q += gsz) {
        int e0 = q * 4;
        int nv = (e0 + 4 <= n_edge) ? 4 : (n_edge - e0);
        int dst[4];
        if (nv == 4) {
            if (!is64) {
                int4 v = *(const int4*)((const int*)edge_index + (size_t)n_edge + e0);
                dst[0] = v.x; dst[1] = v.y; dst[2] = v.z; dst[3] = v.w;
            } else {
                longlong2 a = *(const longlong2*)((const long long*)edge_index + (size_t)n_edge + e0);
                longlong2 b = *(const longlong2*)((const long long*)edge_index + (size_t)n_edge + e0 + 2);
                dst[0] = (int)a.x; dst[1] = (int)a.y; dst[2] = (int)b.x; dst[3] = (int)b.y;
            }
        } else {
            for (int k = 0; k < nv; k++)
                dst[k] = ld_idx(edge_index, (size_t)n_edge + e0 + k, is64);
        }
#pragma unroll
        for (int k = 0; k < 4; k++) {
            if (k >= nv) break;
            if (!(g_bits[dst[k] >> 5] & (1u << (dst[k] & 31)))) continue;
            int s = g_slot[dst[k]] - 2;
            int e   = e0 + k;
            int r   = ld_idx(edge_type, e, is64);
            int src = ld_idx(edge_index, e, is64);
            atomicAdd(&g_cnt[s * n_rel + r], 1.0f);
            const float4* xs = (const float4*)(x + (size_t)src * DIM);
            float* m = &g_msg[((size_t)s * n_rel + r) * DIM];
#pragma unroll
            for (int j = 0; j < DIM / 4; j++) {
                float4 v = xs[j];
                atomicAdd(&m[4 * j + 0], v.x);
                atomicAdd(&m[4 * j + 1], v.y);
                atomicAdd(&m[4 * j + 2], v.z);
                atomicAdd(&m[4 * j + 3], v.w);
            }
        }
    }
}

// ============ 2) k_gemm: per-(rel, half, slot-group), R6 config ============
// grid = (n_rel + 1) * 2 * GROUPS blocks of 128 threads.
__global__ void __launch_bounds__(128)
k_gemm(const float* __restrict__ W_rel,
       const float* __restrict__ W_root,
       const float* __restrict__ x,
       int n_rel) {
    __shared__ float Ws[64 * DIM];   // one 64-col half, Ws[d * 64 + c]
    __shared__ float ms[DIM];

    int idx  = blockIdx.x;
    int r    = idx % (n_rel + 1);
    int half = (idx / (n_rel + 1)) & 1;
    int sg   = idx / ((n_rel + 1) * 2);
    const float* W = (r < n_rel) ? (W_rel + (size_t)r * DIM * DIM) : W_root;
    int tid = threadIdx.x;
    int nn = g_n_needed;

    int fbase = half * 64;
    for (int i = tid; i < 64 * DIM / 4; i += 128) {
        int d = i >> 4, c4 = i & 15;
        ((float4*)Ws)[d * 16 + c4] = *(const float4*)&W[d * DIM + fbase + c4 * 4];
    }
    __syncthreads();

    int c  = tid & 63;
    int dh = (tid >> 6) * 64;

    for (int s = sg; s < nn; s += GROUPS) {
        bool skip = false;
        float scale = 1.0f;
        if (r < n_rel) {
            float cnt = g_cnt[s * n_rel + r];    // uniform across block
            if (cnt == 0.0f) skip = true;
            else scale = 1.0f / cnt;
        }
        if (!skip) {
            if (r < n_rel)
                ms[tid] = g_msg[((size_t)s * n_rel + r) * DIM + tid] * scale;
            else
                ms[tid] = x[(size_t)g_needed_nodes[s] * DIM + tid];
        }
        __syncthreads();
        if (!skip) {
            float acc = 0.0f;
#pragma unroll
            for (int k = 0; k < 16; k++) {
                int d = dh + k * 4;
                float4 mv = *(const float4*)&ms[d];
                acc += mv.x * Ws[(d + 0) * 64 + c];
                acc += mv.y * Ws[(d + 1) * 64 + c];
                acc += mv.z * Ws[(d + 2) * 64 + c];
                acc += mv.w * Ws[(d + 3) * 64 + c];
            }
            atomicAdd(&g_agg[s * DIM + fbase + c], acc);
        }
        __syncthreads();
    }
}

// ============ 3) k_oc: out + msg/cnt zero | barrier | cleanup ==============
// grid = OC_BLK blocks x 256 (batch warps for the gather phase).
__global__ void __launch_bounds__(256, 2)
k_oc(const void* __restrict__ sample,
     const float* __restrict__ init_rel,
     float* __restrict__ out,
     int batch, int n_rel) {
    const int tid  = threadIdx.x;
    const int gtid = blockIdx.x * 256 + tid;
    const int gsz  = gridDim.x * 256;
    const int nn   = g_n_needed;     // read at entry (reset happens post-barrier)
    const int is64 = g_is64;

    // ---- phase 1a: zero msg/cnt (not read here; gemm already consumed) ----
    {
        float4 z = make_float4(0.f, 0.f, 0.f, 0.f);
        int n_msg4 = nn * n_rel * (DIM / 4);
        for (int i = gtid; i < n_msg4; i += gsz) ((float4*)g_msg)[i] = z;
        int n_cnt = nn * n_rel;
        for (int i = gtid; i < n_cnt; i += gsz) g_cnt[i] = 0.0f;
    }

    // ---- phase 1b: warp-per-row gather epilogue ---------------------------
    {
        int w    = gtid >> 5;
        int lane = tid & 31;
        if (w < batch) {
            int sh = 0, st = 0, rel = 0;
            if (lane == 0) {
                int h = ld_idx(sample, (size_t)w * 3 + 0, is64);
                rel   = ld_idx(sample, (size_t)w * 3 + 1, is64);
                int t = ld_idx(sample, (size_t)w * 3 + 2, is64);
                sh = g_slot[h] - 2;
                st = g_slot[t] - 2;
            }
            sh  = __shfl_sync(0xffffffffu, sh, 0);
            st  = __shfl_sync(0xffffffffu, st, 0);
            rel = __shfl_sync(0xffffffffu, rel, 0);

            float4 ah = ((const float4*)g_agg)[sh * (DIM / 4) + lane];
            float4 at = ((const float4*)g_agg)[st * (DIM / 4) + lane];
            float4 rv = ((const float4*)init_rel)[rel * (DIM / 4) + lane];
            float4 o;
            o.x = ftanh(ah.x) * (rv.x * ftanh(at.x));
            o.y = ftanh(ah.y) * (rv.y * ftanh(at.y));
            o.z = ftanh(ah.z) * (rv.z * ftanh(at.z));
            o.w = ftanh(ah.w) * (rv.w * ftanh(at.w));
            ((float4*)out)[(size_t)w * (DIM / 4) + lane] = o;
        }
    }
    barrier_sr(&g_cntB, &g_senseB, gridDim.x);

    // ---- phase 2: cleanup (agg, bits, slot, counter) ----------------------
    {
        float4 z = make_float4(0.f, 0.f, 0.f, 0.f);
        int n_agg4 = nn * (DIM / 4);
        for (int i = gtid; i < n_agg4; i += gsz) ((float4*)g_agg)[i] = z;
        for (int i = gtid; i < nn; i += gsz) {
            int node = g_needed_nodes[i];
            g_slot[node] = 0;
            g_bits[node >> 5] = 0u;   // every set bit belongs to a needed node
        }
        if (gtid == 0) g_n_needed = 0;
    }
}

// ---------------- launch ----------------
extern "C" void kernel_launch(void* const* d_in, const int* in_sizes, int n_in,
                              void* d_out, int out_size) {
    const float* init_embed = (const float*)d_in[0];
    const float* init_rel   = (const float*)d_in[1];
    const float* W_rel      = (const float*)d_in[2];
    const float* W_root     = (const float*)d_in[3];
    const void*  edge_index = d_in[4];
    const void*  edge_type  = d_in[5];
    const void*  sample     = d_in[6];
    float* out = (float*)d_out;

    int n_rel  = in_sizes[1] / DIM;
    int n_edge = in_sizes[5];
    int batch  = in_sizes[6] / 3;

    k_ms  <<<MS_BLK, 256>>>(edge_index, edge_type, init_embed, sample,
                            n_edge, n_rel, batch);
    k_gemm<<<(n_rel + 1) * 2 * GROUPS, 128>>>(W_rel, W_root, init_embed, n_rel);
    k_oc  <<<OC_BLK, 256>>>(sample, init_rel, out, batch, n_rel);
}